// round 5
// baseline (speedup 1.0000x reference)
#include <cuda_runtime.h>
#include <cstdint>

#define T_STEPS 2048
#define BATCH   4096
#define HID     4
#define LAYERS  3
#define TILE    32      // batch elems per block
#define D_PF    16      // x prefetch ring depth (slots)

// Fast, accurate-enough tanh: (e^{2x}-1)/(e^{2x}+1) with ex2/rcp approx MUFUs.
// ~1e-6 rel error per evaluation; recurrence is contractive so no blowup.
__device__ __forceinline__ float tanh_fast(float x) {
    float xc = fminf(fmaxf(x, -15.0f), 15.0f);   // keep e^{2x} finite
    float e  = __expf(2.0f * xc);                // FMUL + MUFU.EX2
    return (e - 1.0f) * __fdividef(1.0f, e + 1.0f);  // FADD,FADD,MUFU.RCP,FMUL
}

__device__ __forceinline__ uint32_t smem_u32(const void* p) {
    return (uint32_t)__cvta_generic_to_shared(p);
}
__device__ __forceinline__ void cp_async16(uint32_t dst, const void* src) {
    asm volatile("cp.async.cg.shared.global [%0], [%1], 16;" :: "r"(dst), "l"(src));
}
__device__ __forceinline__ void cp_commit() {
    asm volatile("cp.async.commit_group;");
}
template<int N>
__device__ __forceinline__ void cp_wait() {
    asm volatile("cp.async.wait_group %0;" :: "n"(N));
}

// Block layout: 4 warps.
//   warp 0,1,2 : compute layer 0,1,2 (software-pipelined: warp l does timestep i-l)
//   warp 3     : x loader (cp.async ring, D_PF slots, D_PF-1 steps of lead)
// Exchange: layer l -> l+1 through double-buffered SMEM, one __syncthreads per
// pipeline iteration. Exchange latency is off the recurrent critical path.
__global__ __launch_bounds__(128, 1)
void rnn_pipe_kernel(const float* __restrict__ x,
                     const float* __restrict__ h0,
                     const float* __restrict__ Wih,
                     const float* __restrict__ Whh,
                     const float* __restrict__ bih,
                     const float* __restrict__ bhh,
                     float* __restrict__ out)
{
    __shared__ float4 xbuf[D_PF][TILE];     // 8 KB x staging ring
    __shared__ float4 ybuf[2][2][TILE];     // [producer layer 0/1][parity][lane]

    const int tid   = threadIdx.x;
    const int warp  = tid >> 5;
    const int lane  = tid & 31;
    const int batch = blockIdx.x * TILE + lane;

    if (warp == 3) {
        // ---------------- loader warp ----------------
        const float4* xg = (const float4*)x;
        #pragma unroll
        for (int k = 0; k < D_PF - 1; k++) {          // prologue: t = 0 .. D_PF-2
            cp_async16(smem_u32(&xbuf[k][lane]), &xg[(size_t)k * BATCH + batch]);
            cp_commit();
        }
        cp_wait<D_PF - 2>();                           // t=0 complete
        __syncthreads();
        for (int i = 0; i < T_STEPS + 2; i++) {
            int t = i + D_PF - 1;
            if (t < T_STEPS) {
                cp_async16(smem_u32(&xbuf[t % D_PF][lane]),
                           &xg[(size_t)t * BATCH + batch]);
                cp_commit();
                cp_wait<D_PF - 2>();   // group for t=i+1 is done before this bar
            } else {
                cp_wait<0>();          // drain tail
            }
            __syncthreads();
        }
    } else {
        // ---------------- compute warp: layer l = warp ----------------
        const int l = warp;
        float wih[4][4], whh[4][4], bb[4], h[4];
        #pragma unroll
        for (int c = 0; c < 4; c++) {
            #pragma unroll
            for (int j = 0; j < 4; j++) {
                wih[c][j] = Wih[l * 16 + c * 4 + j];
                whh[c][j] = Whh[l * 16 + c * 4 + j];
            }
            bb[c] = bih[l * 4 + c] + bhh[l * 4 + c];
        }
        {
            float4 hv = ((const float4*)h0)[(size_t)l * BATCH + batch];
            h[0] = hv.x; h[1] = hv.y; h[2] = hv.z; h[3] = hv.w;
        }
        __syncthreads();   // matches loader prologue sync

        for (int i = 0; i < T_STEPS + 2; i++) {
            int t = i - l;
            if (t >= 0 && t < T_STEPS) {
                float4 in;
                if (l == 0) in = xbuf[t % D_PF][lane];
                else        in = ybuf[l - 1][i & 1][lane];

                float a[4];
                #pragma unroll
                for (int c = 0; c < 4; c++) {
                    float s = bb[c];
                    s = fmaf(wih[c][0], in.x, s);
                    s = fmaf(wih[c][1], in.y, s);
                    s = fmaf(wih[c][2], in.z, s);
                    s = fmaf(wih[c][3], in.w, s);
                    s = fmaf(whh[c][0], h[0], s);
                    s = fmaf(whh[c][1], h[1], s);
                    s = fmaf(whh[c][2], h[2], s);
                    s = fmaf(whh[c][3], h[3], s);
                    a[c] = s;
                }
                #pragma unroll
                for (int c = 0; c < 4; c++) h[c] = tanh_fast(a[c]);

                float4 ov = make_float4(h[0], h[1], h[2], h[3]);
                if (l == 2) ((float4*)out)[(size_t)t * BATCH + batch] = ov;
                else        ybuf[l][(i + 1) & 1][lane] = ov;
            }
            __syncthreads();
        }
    }
}

extern "C" void kernel_launch(void* const* d_in, const int* in_sizes, int n_in,
                              void* d_out, int out_size) {
    const float* x   = (const float*)d_in[0];
    const float* h0  = (const float*)d_in[1];
    const float* Wih = (const float*)d_in[2];
    const float* Whh = (const float*)d_in[3];
    const float* bih = (const float*)d_in[4];
    const float* bhh = (const float*)d_in[5];
    float* out = (float*)d_out;

    dim3 grid(BATCH / TILE);   // 128 blocks
    dim3 block(128);           // 4 warps: 3 layer warps + 1 loader warp
    rnn_pipe_kernel<<<grid, block>>>(x, h0, Wih, Whh, bih, bhh, out);
}